// round 4
// baseline (speedup 1.0000x reference)
#include <cuda_runtime.h>
#include <math.h>

// GRU: B=256, T=512, H=512, L=2, O=2.
// Persistent-kernel fp32 implementation.
//
// Per step t (pipelined across steps):
//   wave:  288 gemm units of 64x64xK512:
//            u in [0,96):    gi1 tile:  h0(t)   @ Wi_rest^T  -> PB0
//            u in [96,192):  gh1 tile:  h1(t-1) @ Wh[1]^T    -> PB1
//            u in [192,288): layer0:    h0(t)   @ Wh[0]^T    -> GA   (for step t+1)
//   grid barrier
//   act:   actB(t): h1(t) from PB0/PB1 ; actA(t+1): h0(t+1) from GA + x[:,t+1]
//   grid barrier
// Final: out = h1(511) @ fc_w^T + fc_b.

#define BT 256      // batch
#define TT 512      // timesteps
#define HH 512      // hidden
#define NG 1536     // 3*H (gate-major columns)
#define KT 16       // k-tile
#define NCTA 148    // <= 152 SMs on GB300 -> all CTAs co-resident
#define NTHR 256

// ---------------- persistent device state (no allocation allowed) ----------------
__device__ __align__(16) float d_h0[BT * HH];
__device__ __align__(16) float d_h1[BT * HH];
__device__ __align__(16) float d_GA[BT * NG];    // layer0 gemm output (gh0, 3 gates)
__device__ __align__(16) float d_PB0[BT * NG];   // layer1 input-gemm output (gi1)
__device__ __align__(16) float d_PB1[BT * NG];   // layer1 hidden-gemm output (gh1)
__device__ unsigned d_barCount;
__device__ volatile unsigned d_barGen;

// ---------------- init: reset state every launch (graph replays must be deterministic)
__global__ void gru_init()
{
    int i  = blockIdx.x * blockDim.x + threadIdx.x;
    int st = gridDim.x * blockDim.x;
    for (int e = i; e < BT * HH; e += st) { d_h0[e] = 0.f; d_h1[e] = 0.f; }
    for (int e = i; e < BT * NG; e += st) d_GA[e] = 0.f;
    if (i == 0) { d_barCount = 0u; d_barGen = 0u; }
}

// ---------------- software grid barrier (all NCTA CTAs are resident) ----------------
__device__ __forceinline__ void gridBarrier()
{
    __syncthreads();
    if (threadIdx.x == 0) {
        __threadfence();                       // release my CTA's writes
        unsigned gen = d_barGen;               // stable until all arrive
        if (atomicAdd(&d_barCount, 1u) == (unsigned)gridDim.x - 1u) {
            d_barCount = 0u;
            __threadfence();
            d_barGen = gen + 1u;               // release
        } else {
            while (d_barGen == gen) __nanosleep(64);
        }
        __threadfence();                       // acquire
    }
    __syncthreads();
}

// ---------------- 64x64 tile gemm, K=512: C[m0..+64, n0..+64] = A @ W^T ----------------
// A: row-major [*, HH]   (h state, rows = batch)
// W: row-major [*, HH]   (weight, rows = output column n' = g*512+n)
// C: row-major [*, NG]
__device__ void gemm64(const float* __restrict__ A, const float* __restrict__ W,
                       float* __restrict__ C, int m0, int n0)
{
    __shared__ float As[2][KT][68];   // [buf][k][m], pad 68 for LDS128 alignment
    __shared__ float Bs[2][KT][68];   // [buf][k][n]

    const int tid = threadIdx.x;
    const int tx  = tid & 15;         // 16 column groups
    const int ty  = tid >> 4;         // 16 row groups
    const int lr  = tid >> 2;         // load row     0..63
    const int lc  = (tid & 3) << 2;   // load k group 0,4,8,12

    const float* Ap = A + (m0 + lr) * HH + lc;
    const float* Wp = W + (n0 + lr) * HH + lc;

    float acc[4][4];
#pragma unroll
    for (int i = 0; i < 4; ++i)
#pragma unroll
        for (int j = 0; j < 4; ++j) acc[i][j] = 0.f;

    __syncthreads();   // protect smem against previous gemm64 call still in flight

    float4 ra = *(const float4*)Ap;
    float4 rb = *(const float4*)Wp;
    As[0][lc + 0][lr] = ra.x; As[0][lc + 1][lr] = ra.y; As[0][lc + 2][lr] = ra.z; As[0][lc + 3][lr] = ra.w;
    Bs[0][lc + 0][lr] = rb.x; Bs[0][lc + 1][lr] = rb.y; Bs[0][lc + 2][lr] = rb.z; Bs[0][lc + 3][lr] = rb.w;
    __syncthreads();

    int buf = 0;
    const int NKT = HH / KT;   // 32
#pragma unroll 1
    for (int kt = 0; kt < NKT; ++kt) {
        if (kt + 1 < NKT) {
            ra = *(const float4*)(Ap + (kt + 1) * KT);
            rb = *(const float4*)(Wp + (kt + 1) * KT);
        }
#pragma unroll
        for (int kk = 0; kk < KT; ++kk) {
            float4 av = *(const float4*)&As[buf][kk][ty << 2];
            float4 bv = *(const float4*)&Bs[buf][kk][tx << 2];
            acc[0][0] += av.x * bv.x; acc[0][1] += av.x * bv.y; acc[0][2] += av.x * bv.z; acc[0][3] += av.x * bv.w;
            acc[1][0] += av.y * bv.x; acc[1][1] += av.y * bv.y; acc[1][2] += av.y * bv.z; acc[1][3] += av.y * bv.w;
            acc[2][0] += av.z * bv.x; acc[2][1] += av.z * bv.y; acc[2][2] += av.z * bv.z; acc[2][3] += av.z * bv.w;
            acc[3][0] += av.w * bv.x; acc[3][1] += av.w * bv.y; acc[3][2] += av.w * bv.z; acc[3][3] += av.w * bv.w;
        }
        if (kt + 1 < NKT) {
            buf ^= 1;  // other buffer was fully consumed at iteration kt-1 (sync below)
            As[buf][lc + 0][lr] = ra.x; As[buf][lc + 1][lr] = ra.y; As[buf][lc + 2][lr] = ra.z; As[buf][lc + 3][lr] = ra.w;
            Bs[buf][lc + 0][lr] = rb.x; Bs[buf][lc + 1][lr] = rb.y; Bs[buf][lc + 2][lr] = rb.z; Bs[buf][lc + 3][lr] = rb.w;
            __syncthreads();
        }
    }

    float* Cp = C + (m0 + (ty << 2)) * NG + (n0 + (tx << 2));
#pragma unroll
    for (int i = 0; i < 4; ++i) {
        float4 v; v.x = acc[i][0]; v.y = acc[i][1]; v.z = acc[i][2]; v.w = acc[i][3];
        *(float4*)(Cp + i * NG) = v;
    }
}

// ---------------- one gemm wave: numU units distributed over the grid ----------------
__device__ void waveUnits(const float* __restrict__ Wi1, const float* __restrict__ Wh, int numU)
{
    for (int u = blockIdx.x; u < numU; u += gridDim.x) {
        const float* A; const float* W; float* C; int tb;
        if (u < 96)        { tb = u;        A = d_h0; W = Wi1;          C = d_PB0; }
        else if (u < 192)  { tb = u - 96;   A = d_h1; W = Wh + NG * HH; C = d_PB1; }
        else               { tb = u - 192;  A = d_h0; W = Wh;           C = d_GA;  }
        int m0 = (tb / 24) << 6;   // 4 M tiles
        int n0 = (tb % 24) << 6;   // 24 N tiles
        gemm64(A, W, C, m0, n0);
    }
}

// ---------------- GRU elementwise ----------------
__device__ __forceinline__ float sigmoidf_(float v) { return 1.f / (1.f + expf(-v)); }

// layer 0 act for step t: h0 = GRU(x[:,t]*Wi0+bi0, GA+bh0, h0_old)
__device__ void actA(const float* __restrict__ x, const float* __restrict__ Wi0,
                     const float* __restrict__ bi0, const float* __restrict__ bh, int t)
{
    int gtid = blockIdx.x * blockDim.x + threadIdx.x;
    int st   = gridDim.x * blockDim.x;
    for (int e = gtid; e < BT * HH; e += st) {
        int b = e >> 9;
        int n = e & (HH - 1);
        float xv  = x[b * TT + t];
        float s0  = d_GA[b * NG + n]           + bh[n]          + xv * Wi0[n]          + bi0[n];
        float s1  = d_GA[b * NG + HH + n]      + bh[HH + n]     + xv * Wi0[HH + n]     + bi0[HH + n];
        float ga2 = d_GA[b * NG + 2 * HH + n]  + bh[2 * HH + n];
        float gi2 = xv * Wi0[2 * HH + n] + bi0[2 * HH + n];
        float r  = sigmoidf_(s0);
        float z  = sigmoidf_(s1);
        float nn = tanhf(gi2 + r * ga2);
        float ho = d_h0[e];
        d_h0[e] = (1.f - z) * nn + z * ho;
    }
}

// layer 1 act: h1 = GRU(PB0+bi_rest, PB1+bh1, h1_old)
__device__ void actB(const float* __restrict__ bi1, const float* __restrict__ bh)
{
    int gtid = blockIdx.x * blockDim.x + threadIdx.x;
    int st   = gridDim.x * blockDim.x;
    for (int e = gtid; e < BT * HH; e += st) {
        int b = e >> 9;
        int n = e & (HH - 1);
        float gi0 = d_PB0[b * NG + n]          + bi1[n];
        float gh0 = d_PB1[b * NG + n]          + bh[NG + n];
        float gi1 = d_PB0[b * NG + HH + n]     + bi1[HH + n];
        float gh1 = d_PB1[b * NG + HH + n]     + bh[NG + HH + n];
        float gi2 = d_PB0[b * NG + 2 * HH + n] + bi1[2 * HH + n];
        float gh2 = d_PB1[b * NG + 2 * HH + n] + bh[NG + 2 * HH + n];
        float r  = sigmoidf_(gi0 + gh0);
        float z  = sigmoidf_(gi1 + gh1);
        float nn = tanhf(gi2 + r * gh2);
        float ho = d_h1[e];
        d_h1[e] = (1.f - z) * nn + z * ho;
    }
}

// ---------------- final FC: out[b][o] = h1[b] . fc_w[o] + fc_b[o] ----------------
__device__ void fcOut(const float* __restrict__ fcw, const float* __restrict__ fcb,
                      float* __restrict__ out)
{
    __shared__ float red[2][8];
    if (blockIdx.x >= 128) return;
    for (int s = 0; s < 2; ++s) {
        int b = blockIdx.x * 2 + s;
        float p0 = 0.f, p1 = 0.f;
        for (int k = threadIdx.x; k < HH; k += NTHR) {
            float h = d_h1[b * HH + k];
            p0 += h * fcw[k];
            p1 += h * fcw[HH + k];
        }
#pragma unroll
        for (int o = 16; o; o >>= 1) {
            p0 += __shfl_down_sync(0xffffffffu, p0, o);
            p1 += __shfl_down_sync(0xffffffffu, p1, o);
        }
        int w = threadIdx.x >> 5;
        if ((threadIdx.x & 31) == 0) { red[0][w] = p0; red[1][w] = p1; }
        __syncthreads();
        if (threadIdx.x == 0) {
            float a0 = 0.f, a1 = 0.f;
#pragma unroll
            for (int ww = 0; ww < 8; ++ww) { a0 += red[0][ww]; a1 += red[1][ww]; }
            out[b * 2 + 0] = a0 + fcb[0];
            out[b * 2 + 1] = a1 + fcb[1];
        }
        __syncthreads();
    }
}

// ---------------- persistent kernel ----------------
__global__ void __launch_bounds__(NTHR, 1)
gru_persistent(const float* __restrict__ x,   const float* __restrict__ Wi0,
               const float* __restrict__ bi0, const float* __restrict__ Wi1,
               const float* __restrict__ bi1, const float* __restrict__ Wh,
               const float* __restrict__ bh,  const float* __restrict__ fcw,
               const float* __restrict__ fcb, float* __restrict__ out)
{
    // prologue: h0(0) from x[:,0] (GA and h0 are zero from init)
    actA(x, Wi0, bi0, bh, 0);
    gridBarrier();

    // pipelined mainloop: wave computes {B(t), A(t+1)}, act computes {h1(t), h0(t+1)}
    for (int t = 0; t < TT - 1; ++t) {
        waveUnits(Wi1, Wh, 288);
        gridBarrier();
        actB(bi1, bh);
        actA(x, Wi0, bi0, bh, t + 1);
        gridBarrier();
    }

    // tail: layer1 of last step
    waveUnits(Wi1, Wh, 192);
    gridBarrier();
    actB(bi1, bh);
    gridBarrier();

    fcOut(fcw, fcb, out);
}

// ---------------- launch ----------------
extern "C" void kernel_launch(void* const* d_in, const int* in_sizes, int n_in,
                              void* d_out, int out_size)
{
    (void)in_sizes; (void)n_in; (void)out_size;
    const float* x   = (const float*)d_in[0];   // (256, 512)
    const float* Wi0 = (const float*)d_in[1];   // (3, 512, 1)
    const float* bi0 = (const float*)d_in[2];   // (3, 512)
    const float* Wi1 = (const float*)d_in[3];   // Wi_rest (1, 3, 512, 512)
    const float* bi1 = (const float*)d_in[4];   // bi_rest (1, 3, 512)
    const float* Wh  = (const float*)d_in[5];   // (2, 3, 512, 512)
    const float* bh  = (const float*)d_in[6];   // (2, 3, 512)
    const float* fcw = (const float*)d_in[7];   // (2, 512)
    const float* fcb = (const float*)d_in[8];   // (2,)
    float* out = (float*)d_out;                 // (256, 2)

    gru_init<<<64, 256>>>();
    gru_persistent<<<NCTA, NTHR>>>(x, Wi0, bi0, Wi1, bi1, Wh, bh, fcw, fcb, out);
}

// round 8
// speedup vs baseline: 1.2520x; 1.2520x over previous
#include <cuda_runtime.h>
#include <math.h>

// GRU: B=256, T=512, H=512, L=2, O=2.  Persistent fp32 kernel (scalar FFMA,
// no inline asm), 128x64 tiles, register double-buffered fragments.
//
// Per step t (pipelined across steps), one wave of 144 gemm tiles (128x64xK512):
//   u in [0,48):    gi1 tile:  h0(t)   @ Wi_rest^T  -> PB0
//   u in [48,96):   gh1 tile:  h1(t-1) @ Wh[1]^T    -> PB1
//   u in [96,144):  layer0:    h0(t)   @ Wh[0]^T    -> GA   (for step t+1)
// grid barrier; fused activations (h1(t), h0(t+1)); grid barrier.
// Final: out = h1(511) @ fc_w^T + fc_b.

#define BT 256
#define TT 512
#define HH 512
#define NG 1536     // 3*H
#define KT 16
#define TM 128
#define TN 64
#define NCTA 148
#define NTHR 256

// ---------------- persistent device state ----------------
__device__ __align__(16) float d_h0[BT * HH];
__device__ __align__(16) float d_h1[BT * HH];
__device__ __align__(16) float d_GA[BT * NG];
__device__ __align__(16) float d_PB0[BT * NG];
__device__ __align__(16) float d_PB1[BT * NG];
__device__ unsigned d_barCount;
__device__ volatile unsigned d_barGen;

__global__ void gru_init()
{
    int i  = blockIdx.x * blockDim.x + threadIdx.x;
    int st = gridDim.x * blockDim.x;
    for (int e = i; e < BT * HH; e += st) { d_h0[e] = 0.f; d_h1[e] = 0.f; }
    for (int e = i; e < BT * NG; e += st) d_GA[e] = 0.f;
    if (i == 0) { d_barCount = 0u; d_barGen = 0u; }
}

// ---------------- software grid barrier (all NCTA CTAs resident) ----------------
__device__ __forceinline__ void gridBarrier()
{
    __syncthreads();
    if (threadIdx.x == 0) {
        __threadfence();
        unsigned gen = d_barGen;
        if (atomicAdd(&d_barCount, 1u) == (unsigned)gridDim.x - 1u) {
            d_barCount = 0u;
            __threadfence();
            d_barGen = gen + 1u;
        } else {
            while (d_barGen == gen) __nanosleep(64);
        }
        __threadfence();
    }
    __syncthreads();
}

// ---------------- 128x64 tile gemm, K=512: C = A @ W^T ----------------
// A row-major [*, HH]; W row-major [*, HH] (row = output col); C row-major [*, NG].
// 256 threads, 8x4 micro-tile, smem double-buffered, fragments reg-double-buffered.
__device__ void gemmTile(const float* __restrict__ A, const float* __restrict__ W,
                         float* __restrict__ C, int m0, int n0)
{
    __shared__ __align__(16) float As[2][KT][TM + 4];   // [buf][k][m]
    __shared__ __align__(16) float Bs[2][KT][TN + 4];   // [buf][k][n]

    const int tid = threadIdx.x;
    const int tx  = tid & 15;          // n group (4 cols)
    const int ty  = tid >> 4;          // m group (8 rows)
    const int lra = tid >> 1;          // A load row 0..127
    const int lca = (tid & 1) << 3;    // A load k offset 0 or 8
    const int lrb = tid >> 2;          // B load row 0..63
    const int lcb = (tid & 3) << 2;    // B load k offset 0,4,8,12

    const float* Ap = A + (m0 + lra) * HH + lca;
    const float* Wp = W + (n0 + lrb) * HH + lcb;

    float acc[8][4];
#pragma unroll
    for (int i = 0; i < 8; ++i)
#pragma unroll
        for (int j = 0; j < 4; ++j) acc[i][j] = 0.f;

    __syncthreads();   // WAR protection across calls

    float4 ra0 = *(const float4*)Ap;
    float4 ra1 = *(const float4*)(Ap + 4);
    float4 rb  = *(const float4*)Wp;
    As[0][lca + 0][lra] = ra0.x; As[0][lca + 1][lra] = ra0.y;
    As[0][lca + 2][lra] = ra0.z; As[0][lca + 3][lra] = ra0.w;
    As[0][lca + 4][lra] = ra1.x; As[0][lca + 5][lra] = ra1.y;
    As[0][lca + 6][lra] = ra1.z; As[0][lca + 7][lra] = ra1.w;
    Bs[0][lcb + 0][lrb] = rb.x;  Bs[0][lcb + 1][lrb] = rb.y;
    Bs[0][lcb + 2][lrb] = rb.z;  Bs[0][lcb + 3][lrb] = rb.w;
    __syncthreads();

    int buf = 0;
    const int NKT = HH / KT;   // 32
#pragma unroll 1
    for (int kt = 0; kt < NKT; ++kt) {
        if (kt + 1 < NKT) {
            ra0 = *(const float4*)(Ap + (kt + 1) * KT);
            ra1 = *(const float4*)(Ap + (kt + 1) * KT + 4);
            rb  = *(const float4*)(Wp + (kt + 1) * KT);
        }

        // register double-buffered fragments: prefetch kk+1 during kk's FMAs
        float4 a0 = *(const float4*)&As[buf][0][ty << 3];
        float4 a1 = *(const float4*)&As[buf][0][(ty << 3) + 4];
        float4 bv = *(const float4*)&Bs[buf][0][tx << 2];
#pragma unroll
        for (int kk = 0; kk < KT; ++kk) {
            float4 na0, na1, nbv;
            if (kk + 1 < KT) {
                na0 = *(const float4*)&As[buf][kk + 1][ty << 3];
                na1 = *(const float4*)&As[buf][kk + 1][(ty << 3) + 4];
                nbv = *(const float4*)&Bs[buf][kk + 1][tx << 2];
            }
            acc[0][0] += a0.x * bv.x; acc[0][1] += a0.x * bv.y; acc[0][2] += a0.x * bv.z; acc[0][3] += a0.x * bv.w;
            acc[1][0] += a0.y * bv.x; acc[1][1] += a0.y * bv.y; acc[1][2] += a0.y * bv.z; acc[1][3] += a0.y * bv.w;
            acc[2][0] += a0.z * bv.x; acc[2][1] += a0.z * bv.y; acc[2][2] += a0.z * bv.z; acc[2][3] += a0.z * bv.w;
            acc[3][0] += a0.w * bv.x; acc[3][1] += a0.w * bv.y; acc[3][2] += a0.w * bv.z; acc[3][3] += a0.w * bv.w;
            acc[4][0] += a1.x * bv.x; acc[4][1] += a1.x * bv.y; acc[4][2] += a1.x * bv.z; acc[4][3] += a1.x * bv.w;
            acc[5][0] += a1.y * bv.x; acc[5][1] += a1.y * bv.y; acc[5][2] += a1.y * bv.z; acc[5][3] += a1.y * bv.w;
            acc[6][0] += a1.z * bv.x; acc[6][1] += a1.z * bv.y; acc[6][2] += a1.z * bv.z; acc[6][3] += a1.z * bv.w;
            acc[7][0] += a1.w * bv.x; acc[7][1] += a1.w * bv.y; acc[7][2] += a1.w * bv.z; acc[7][3] += a1.w * bv.w;
            if (kk + 1 < KT) { a0 = na0; a1 = na1; bv = nbv; }
        }

        if (kt + 1 < NKT) {
            buf ^= 1;
            As[buf][lca + 0][lra] = ra0.x; As[buf][lca + 1][lra] = ra0.y;
            As[buf][lca + 2][lra] = ra0.z; As[buf][lca + 3][lra] = ra0.w;
            As[buf][lca + 4][lra] = ra1.x; As[buf][lca + 5][lra] = ra1.y;
            As[buf][lca + 6][lra] = ra1.z; As[buf][lca + 7][lra] = ra1.w;
            Bs[buf][lcb + 0][lrb] = rb.x;  Bs[buf][lcb + 1][lrb] = rb.y;
            Bs[buf][lcb + 2][lrb] = rb.z;  Bs[buf][lcb + 3][lrb] = rb.w;
            __syncthreads();
        }
    }

    float* Cp = C + (m0 + (ty << 3)) * NG + (n0 + (tx << 2));
#pragma unroll
    for (int i = 0; i < 8; ++i) {
        float4 v; v.x = acc[i][0]; v.y = acc[i][1]; v.z = acc[i][2]; v.w = acc[i][3];
        *(float4*)(Cp + i * NG) = v;
    }
}

// ---------------- gemm wave: numU 128x64 tiles over the grid ----------------
__device__ void waveUnits(const float* __restrict__ Wi1, const float* __restrict__ Wh, int numU)
{
    for (int u = blockIdx.x; u < numU; u += gridDim.x) {
        const float* A; const float* W; float* C; int tb;
        if (u < 48)       { tb = u;      A = d_h0; W = Wi1;          C = d_PB0; }
        else if (u < 96)  { tb = u - 48; A = d_h1; W = Wh + NG * HH; C = d_PB1; }
        else              { tb = u - 96; A = d_h0; W = Wh;           C = d_GA;  }
        int m0 = (tb / 24) << 7;   // 2 M tiles of 128
        int n0 = (tb % 24) << 6;   // 24 N tiles of 64
        gemmTile(A, W, C, m0, n0);
    }
}

// ---------------- activations (exact, round-4-proven) ----------------
__device__ __forceinline__ float sigmoidf_(float v) { return 1.f / (1.f + expf(-v)); }

// layer 0, step t: h0 = GRU(x[:,t]*Wi0+bi0, GA+bh0, h0_old)
__device__ void actA(const float* __restrict__ x, const float* __restrict__ Wi0,
                     const float* __restrict__ bi0, const float* __restrict__ bh, int t)
{
    int gtid = blockIdx.x * blockDim.x + threadIdx.x;
    int st   = gridDim.x * blockDim.x;
    for (int idx = gtid; idx < (BT * HH) / 4; idx += st) {
        int b = idx >> 7;
        int n = (idx & 127) << 2;
        float xv = x[b * TT + t];
        const float* G = d_GA + b * NG + n;
        float4 g0 = *(const float4*)(G);
        float4 g1 = *(const float4*)(G + HH);
        float4 g2 = *(const float4*)(G + 2 * HH);
        float4 w0 = *(const float4*)(Wi0 + n);
        float4 w1 = *(const float4*)(Wi0 + HH + n);
        float4 w2 = *(const float4*)(Wi0 + 2 * HH + n);
        float4 c0 = *(const float4*)(bi0 + n);
        float4 c1 = *(const float4*)(bi0 + HH + n);
        float4 c2 = *(const float4*)(bi0 + 2 * HH + n);
        float4 d0 = *(const float4*)(bh + n);
        float4 d1 = *(const float4*)(bh + HH + n);
        float4 d2 = *(const float4*)(bh + 2 * HH + n);
        float4 ho = *(const float4*)(d_h0 + b * HH + n);
        float4 res;
        const float* pg0 = (const float*)&g0; const float* pg1 = (const float*)&g1;
        const float* pg2 = (const float*)&g2;
        const float* pw0 = (const float*)&w0; const float* pw1 = (const float*)&w1;
        const float* pw2 = (const float*)&w2;
        const float* pc0 = (const float*)&c0; const float* pc1 = (const float*)&c1;
        const float* pc2 = (const float*)&c2;
        const float* pd0 = (const float*)&d0; const float* pd1 = (const float*)&d1;
        const float* pd2 = (const float*)&d2;
        const float* pho = (const float*)&ho;
        float* pr = (float*)&res;
#pragma unroll
        for (int l = 0; l < 4; ++l) {
            float r  = sigmoidf_(pg0[l] + pd0[l] + xv * pw0[l] + pc0[l]);
            float z  = sigmoidf_(pg1[l] + pd1[l] + xv * pw1[l] + pc1[l]);
            float nn = tanhf(xv * pw2[l] + pc2[l] + r * (pg2[l] + pd2[l]));
            pr[l] = (1.f - z) * nn + z * pho[l];
        }
        *(float4*)(d_h0 + b * HH + n) = res;
    }
}

// layer 1: h1 = GRU(PB0+bi_rest, PB1+bh1, h1_old)
__device__ void actB(const float* __restrict__ bi1, const float* __restrict__ bh)
{
    int gtid = blockIdx.x * blockDim.x + threadIdx.x;
    int st   = gridDim.x * blockDim.x;
    for (int idx = gtid; idx < (BT * HH) / 4; idx += st) {
        int b = idx >> 7;
        int n = (idx & 127) << 2;
        const float* P0 = d_PB0 + b * NG + n;
        const float* P1 = d_PB1 + b * NG + n;
        float4 i0 = *(const float4*)(P0);
        float4 i1 = *(const float4*)(P0 + HH);
        float4 i2 = *(const float4*)(P0 + 2 * HH);
        float4 h0g = *(const float4*)(P1);
        float4 h1g = *(const float4*)(P1 + HH);
        float4 h2g = *(const float4*)(P1 + 2 * HH);
        float4 c0 = *(const float4*)(bi1 + n);
        float4 c1 = *(const float4*)(bi1 + HH + n);
        float4 c2 = *(const float4*)(bi1 + 2 * HH + n);
        float4 d0 = *(const float4*)(bh + NG + n);
        float4 d1 = *(const float4*)(bh + NG + HH + n);
        float4 d2 = *(const float4*)(bh + NG + 2 * HH + n);
        float4 ho = *(const float4*)(d_h1 + b * HH + n);
        float4 res;
        const float* pi0 = (const float*)&i0; const float* pi1 = (const float*)&i1;
        const float* pi2 = (const float*)&i2;
        const float* ph0 = (const float*)&h0g; const float* ph1 = (const float*)&h1g;
        const float* ph2 = (const float*)&h2g;
        const float* pc0 = (const float*)&c0; const float* pc1 = (const float*)&c1;
        const float* pc2 = (const float*)&c2;
        const float* pd0 = (const float*)&d0; const float* pd1 = (const float*)&d1;
        const float* pd2 = (const float*)&d2;
        const float* pho = (const float*)&ho;
        float* pr = (float*)&res;
#pragma unroll
        for (int l = 0; l < 4; ++l) {
            float r  = sigmoidf_(pi0[l] + pc0[l] + ph0[l] + pd0[l]);
            float z  = sigmoidf_(pi1[l] + pc1[l] + ph1[l] + pd1[l]);
            float nn = tanhf(pi2[l] + pc2[l] + r * (ph2[l] + pd2[l]));
            pr[l] = (1.f - z) * nn + z * pho[l];
        }
        *(float4*)(d_h1 + b * HH + n) = res;
    }
}

// ---------------- final FC ----------------
__device__ void fcOut(const float* __restrict__ fcw, const float* __restrict__ fcb,
                      float* __restrict__ out)
{
    __shared__ float red[2][8];
    if (blockIdx.x >= 128) return;
    for (int s = 0; s < 2; ++s) {
        int b = blockIdx.x * 2 + s;
        float p0 = 0.f, p1 = 0.f;
        for (int k = threadIdx.x; k < HH; k += NTHR) {
            float h = d_h1[b * HH + k];
            p0 += h * fcw[k];
            p1 += h * fcw[HH + k];
        }
#pragma unroll
        for (int o = 16; o; o >>= 1) {
            p0 += __shfl_down_sync(0xffffffffu, p0, o);
            p1 += __shfl_down_sync(0xffffffffu, p1, o);
        }
        int w = threadIdx.x >> 5;
        if ((threadIdx.x & 31) == 0) { red[0][w] = p0; red[1][w] = p1; }
        __syncthreads();
        if (threadIdx.x == 0) {
            float a0 = 0.f, a1 = 0.f;
#pragma unroll
            for (int ww = 0; ww < 8; ++ww) { a0 += red[0][ww]; a1 += red[1][ww]; }
            out[b * 2 + 0] = a0 + fcb[0];
            out[b * 2 + 1] = a1 + fcb[1];
        }
        __syncthreads();
    }
}

// ---------------- persistent kernel ----------------
__global__ void __launch_bounds__(NTHR, 1)
gru_persistent(const float* __restrict__ x,   const float* __restrict__ Wi0,
               const float* __restrict__ bi0, const float* __restrict__ Wi1,
               const float* __restrict__ bi1, const float* __restrict__ Wh,
               const float* __restrict__ bh,  const float* __restrict__ fcw,
               const float* __restrict__ fcb, float* __restrict__ out)
{
    actA(x, Wi0, bi0, bh, 0);         // h0(0); GA/h0 zeroed by init
    gridBarrier();

    for (int t = 0; t < TT - 1; ++t) {
        waveUnits(Wi1, Wh, 144);      // {gi1(t), gh1(t), layer0 gh0 for t+1}
        gridBarrier();
        actB(bi1, bh);                // h1(t)
        actA(x, Wi0, bi0, bh, t + 1); // h0(t+1)
        gridBarrier();
    }

    waveUnits(Wi1, Wh, 96);           // last step: layer-1 gemms only
    gridBarrier();
    actB(bi1, bh);
    gridBarrier();

    fcOut(fcw, fcb, out);
}

// ---------------- launch ----------------
extern "C" void kernel_launch(void* const* d_in, const int* in_sizes, int n_in,
                              void* d_out, int out_size)
{
    (void)in_sizes; (void)n_in; (void)out_size;
    const float* x   = (const float*)d_in[0];
    const float* Wi0 = (const float*)d_in[1];
    const float* bi0 = (const float*)d_in[2];
    const float* Wi1 = (const float*)d_in[3];
    const float* bi1 = (const float*)d_in[4];
    const float* Wh  = (const float*)d_in[5];
    const float* bh  = (const float*)d_in[6];
    const float* fcw = (const float*)d_in[7];
    const float* fcb = (const float*)d_in[8];
    float* out = (float*)d_out;

    gru_init<<<64, 256>>>();
    gru_persistent<<<NCTA, NTHR>>>(x, Wi0, bi0, Wi1, bi1, Wh, bh, fcw, fcb, out);
}

// round 9
// speedup vs baseline: 2.0294x; 1.6209x over previous
#include <cuda_runtime.h>
#include <cuda_bf16.h>
#include <math.h>

// GRU: B=256, T=512, H=512, L=2, O=2.
// Persistent kernel, bf16 hi/lo split GEMM on mma.sync.m16n8k16 (fp32 accum).
//
// 144 fixed 128x64 output tiles, one per CTA (CTAs 144..147 help only with
// activations/barriers). Each CTA pins its 64x512 weight slice in smem as
// bf16 hi/lo for the whole run. Per step: one wave of tile-gemms
// (gi1, gh1, layer0-next), grid barrier, fused activations (also emit h as
// bf16 hi/lo), grid barrier. Final: out = h1 @ fc_w^T + fc_b.

#define BT 256
#define TT 512
#define HH 512
#define NG 1536
#define NCTA 148
#define NTHR 256

#define WST 520                       // W smem row stride (bf16 elems), pad for banks
#define AST 40                        // A smem row stride (bf16 elems)
#define SMEM_W (64 * WST * 2)         // 66,560 B per W array
#define SMEM_A_ONE (128 * AST * 2)    // 10,240 B per (buf, hi/lo)
#define SMEM_BYTES (2 * SMEM_W + 4 * SMEM_A_ONE)   // 174,080 B

// ---------------- persistent device state ----------------
__device__ __align__(16) float d_h0[BT * HH];
__device__ __align__(16) float d_h1[BT * HH];
__device__ __align__(16) __nv_bfloat16 d_h0hi[BT * HH];
__device__ __align__(16) __nv_bfloat16 d_h0lo[BT * HH];
__device__ __align__(16) __nv_bfloat16 d_h1hi[BT * HH];
__device__ __align__(16) __nv_bfloat16 d_h1lo[BT * HH];
__device__ __align__(16) float d_GA[BT * NG];
__device__ __align__(16) float d_PB0[BT * NG];
__device__ __align__(16) float d_PB1[BT * NG];
__device__ unsigned d_barCount;
__device__ volatile unsigned d_barGen;

__global__ void gru_init()
{
    int i  = blockIdx.x * blockDim.x + threadIdx.x;
    int st = gridDim.x * blockDim.x;
    for (int e = i; e < BT * HH; e += st) { d_h0[e] = 0.f; d_h1[e] = 0.f; }
    unsigned* z0 = (unsigned*)d_h0hi; unsigned* z1 = (unsigned*)d_h0lo;
    unsigned* z2 = (unsigned*)d_h1hi; unsigned* z3 = (unsigned*)d_h1lo;
    for (int e = i; e < (BT * HH) / 2; e += st) { z0[e] = 0u; z1[e] = 0u; z2[e] = 0u; z3[e] = 0u; }
    for (int e = i; e < BT * NG; e += st) d_GA[e] = 0.f;
    if (i == 0) { d_barCount = 0u; d_barGen = 0u; }
}

// ---------------- software grid barrier (all NCTA CTAs resident) ----------------
__device__ __forceinline__ void gridBarrier()
{
    __syncthreads();
    if (threadIdx.x == 0) {
        __threadfence();
        unsigned gen = d_barGen;
        if (atomicAdd(&d_barCount, 1u) == (unsigned)gridDim.x - 1u) {
            d_barCount = 0u;
            __threadfence();
            d_barGen = gen + 1u;
        } else {
            while (d_barGen == gen) __nanosleep(64);
        }
        __threadfence();
    }
    __syncthreads();
}

// ---------------- bf16 split helpers ----------------
__device__ __forceinline__ unsigned pack_bf2(float a, float b)
{
    __nv_bfloat162 t = __floats2bfloat162_rn(a, b);   // .x = a (low half)
    return *reinterpret_cast<unsigned*>(&t);
}
__device__ __forceinline__ float bflo(float v)
{
    return v - __bfloat162float(__float2bfloat16_rn(v));
}

// mma.sync m16n8k16 row.col bf16 -> f32
#define MMA16816(C, A, b0, b1)                                                  \
    asm volatile("mma.sync.aligned.m16n8k16.row.col.f32.bf16.bf16.f32 "         \
                 "{%0,%1,%2,%3},{%4,%5,%6,%7},{%8,%9},{%0,%1,%2,%3};"           \
                 : "+f"((C)[0]), "+f"((C)[1]), "+f"((C)[2]), "+f"((C)[3])       \
                 : "r"((A)[0]), "r"((A)[1]), "r"((A)[2]), "r"((A)[3]),          \
                   "r"(b0), "r"(b1))

// ---------------- one-time weight slice -> smem (bf16 hi/lo) ----------------
__device__ void preloadW(const float* __restrict__ Wsl, char* smem)
{
    __nv_bfloat16* Whi = (__nv_bfloat16*)(smem);
    __nv_bfloat16* Wlo = (__nv_bfloat16*)(smem + SMEM_W);
    for (int idx = threadIdx.x; idx < 64 * (HH / 4); idx += NTHR) {
        int n  = idx >> 7;             // 0..63
        int k4 = (idx & 127) << 2;     // 0..508
        float4 w = *(const float4*)(Wsl + n * HH + k4);
        uint2 hv, lv;
        hv.x = pack_bf2(w.x, w.y);          hv.y = pack_bf2(w.z, w.w);
        lv.x = pack_bf2(bflo(w.x), bflo(w.y)); lv.y = pack_bf2(bflo(w.z), bflo(w.w));
        *(uint2*)(Whi + n * WST + k4) = hv;
        *(uint2*)(Wlo + n * WST + k4) = lv;
    }
}

// ---------------- 128x64xK512 tile gemm: C = A @ W^T (split bf16, fp32 accum) ----------------
// Agh/Agl: bf16 hi/lo of A, row-major [BT][HH].  W pinned in smem.  C row-major [*, NG].
__device__ void tileStep(const __nv_bfloat16* __restrict__ Agh,
                         const __nv_bfloat16* __restrict__ Agl,
                         float* __restrict__ Cg, int m0, int n0, char* smem)
{
    __nv_bfloat16* Whi = (__nv_bfloat16*)(smem);
    __nv_bfloat16* Wlo = (__nv_bfloat16*)(smem + SMEM_W);
    __nv_bfloat16* Ab  = (__nv_bfloat16*)(smem + 2 * SMEM_W);   // [buf*2+hl][128*AST]

    const int tid  = threadIdx.x;
    const int wid  = tid >> 5;
    const int lane = tid & 31;
    const int g    = lane >> 2;        // 0..7
    const int t4   = lane & 3;         // 0..3
    const int wm   = wid & 1;          // m half (64)
    const int wn   = wid >> 1;         // n quarter (16)

    // A staging: each thread loads 2x uint4 (hi) + 2x uint4 (lo) per 32-k chunk
    const int sr = tid >> 1;            // 0..127
    const int sk = (tid & 1) << 4;      // 0 or 16
    const __nv_bfloat16* Aghp = Agh + (m0 + sr) * HH + sk;
    const __nv_bfloat16* Aglp = Agl + (m0 + sr) * HH + sk;

    int aoff[4];
#pragma unroll
    for (int ma = 0; ma < 4; ++ma)
        aoff[ma] = (wm * 64 + ma * 16 + g) * AST + 2 * t4;
    int boff[2];
#pragma unroll
    for (int na = 0; na < 2; ++na)
        boff[na] = (wn * 16 + na * 8 + g) * WST + 2 * t4;

    float acc[4][2][4];
#pragma unroll
    for (int ma = 0; ma < 4; ++ma)
#pragma unroll
        for (int na = 0; na < 2; ++na)
#pragma unroll
            for (int q = 0; q < 4; ++q) acc[ma][na][q] = 0.f;

    // prefetch + store chunk 0
    uint4 ph0 = *(const uint4*)(Aghp);
    uint4 ph1 = *(const uint4*)(Aghp + 8);
    uint4 pl0 = *(const uint4*)(Aglp);
    uint4 pl1 = *(const uint4*)(Aglp + 8);
    __syncthreads();                          // WAR vs previous step's reads
    {
        __nv_bfloat16* dh = Ab + 0 * 5120 + sr * AST + sk;
        __nv_bfloat16* dl = Ab + 1 * 5120 + sr * AST + sk;
        *(uint4*)dh = ph0; *(uint4*)(dh + 8) = ph1;
        *(uint4*)dl = pl0; *(uint4*)(dl + 8) = pl1;
    }
    __syncthreads();

    int buf = 0;
#pragma unroll 1
    for (int c = 0; c < 16; ++c) {
        if (c + 1 < 16) {
            ph0 = *(const uint4*)(Aghp + (c + 1) * 32);
            ph1 = *(const uint4*)(Aghp + (c + 1) * 32 + 8);
            pl0 = *(const uint4*)(Aglp + (c + 1) * 32);
            pl1 = *(const uint4*)(Aglp + (c + 1) * 32 + 8);
        }
        const __nv_bfloat16* Ah = Ab + (buf * 2 + 0) * 5120;
        const __nv_bfloat16* Al = Ab + (buf * 2 + 1) * 5120;
#pragma unroll
        for (int ks = 0; ks < 32; ks += 16) {
            unsigned ah[4][4], al[4][4];
#pragma unroll
            for (int ma = 0; ma < 4; ++ma) {
                int o = aoff[ma] + ks;
                ah[ma][0] = *(const unsigned*)(Ah + o);
                ah[ma][1] = *(const unsigned*)(Ah + o + 8 * AST);
                ah[ma][2] = *(const unsigned*)(Ah + o + 8);
                ah[ma][3] = *(const unsigned*)(Ah + o + 8 * AST + 8);
                al[ma][0] = *(const unsigned*)(Al + o);
                al[ma][1] = *(const unsigned*)(Al + o + 8 * AST);
                al[ma][2] = *(const unsigned*)(Al + o + 8);
                al[ma][3] = *(const unsigned*)(Al + o + 8 * AST + 8);
            }
#pragma unroll
            for (int na = 0; na < 2; ++na) {
                int ob = boff[na] + c * 32 + ks;
                unsigned bh0 = *(const unsigned*)(Whi + ob);
                unsigned bh1 = *(const unsigned*)(Whi + ob + 8);
                unsigned bl0 = *(const unsigned*)(Wlo + ob);
                unsigned bl1 = *(const unsigned*)(Wlo + ob + 8);
#pragma unroll
                for (int ma = 0; ma < 4; ++ma) {
                    MMA16816(acc[ma][na], ah[ma], bh0, bh1);   // hi*hi
                    MMA16816(acc[ma][na], ah[ma], bl0, bl1);   // hi*lo
                    MMA16816(acc[ma][na], al[ma], bh0, bh1);   // lo*hi
                }
            }
        }
        if (c + 1 < 16) {
            buf ^= 1;
            __nv_bfloat16* dh = Ab + (buf * 2 + 0) * 5120 + sr * AST + sk;
            __nv_bfloat16* dl = Ab + (buf * 2 + 1) * 5120 + sr * AST + sk;
            *(uint4*)dh = ph0; *(uint4*)(dh + 8) = ph1;
            *(uint4*)dl = pl0; *(uint4*)(dl + 8) = pl1;
            __syncthreads();
        }
    }

    // epilogue: per-lane fragment layout of C (m16n8)
#pragma unroll
    for (int ma = 0; ma < 4; ++ma) {
        int row = m0 + wm * 64 + ma * 16 + g;
#pragma unroll
        for (int na = 0; na < 2; ++na) {
            int col = n0 + wn * 16 + na * 8 + 2 * t4;
            float2 v0; v0.x = acc[ma][na][0]; v0.y = acc[ma][na][1];
            float2 v1; v1.x = acc[ma][na][2]; v1.y = acc[ma][na][3];
            *(float2*)(Cg + row * NG + col)       = v0;
            *(float2*)(Cg + (row + 8) * NG + col) = v1;
        }
    }
}

// ---------------- activations (exact; also emit bf16 hi/lo of h) ----------------
__device__ __forceinline__ float sigmoidf_(float v) { return 1.f / (1.f + expf(-v)); }

__device__ void actA(const float* __restrict__ x, const float* __restrict__ Wi0,
                     const float* __restrict__ bi0, const float* __restrict__ bh, int t)
{
    int gtid = blockIdx.x * blockDim.x + threadIdx.x;
    int st   = gridDim.x * blockDim.x;
    for (int idx = gtid; idx < (BT * HH) / 4; idx += st) {
        int b = idx >> 7;
        int n = (idx & 127) << 2;
        float xv = x[b * TT + t];
        const float* G = d_GA + b * NG + n;
        float4 g0 = *(const float4*)(G);
        float4 g1 = *(const float4*)(G + HH);
        float4 g2 = *(const float4*)(G + 2 * HH);
        float4 w0 = *(const float4*)(Wi0 + n);
        float4 w1 = *(const float4*)(Wi0 + HH + n);
        float4 w2 = *(const float4*)(Wi0 + 2 * HH + n);
        float4 c0 = *(const float4*)(bi0 + n);
        float4 c1 = *(const float4*)(bi0 + HH + n);
        float4 c2 = *(const float4*)(bi0 + 2 * HH + n);
        float4 d0 = *(const float4*)(bh + n);
        float4 d1 = *(const float4*)(bh + HH + n);
        float4 d2 = *(const float4*)(bh + 2 * HH + n);
        float4 ho = *(const float4*)(d_h0 + b * HH + n);
        float4 res;
        const float* pg0 = (const float*)&g0; const float* pg1 = (const float*)&g1;
        const float* pg2 = (const float*)&g2;
        const float* pw0 = (const float*)&w0; const float* pw1 = (const float*)&w1;
        const float* pw2 = (const float*)&w2;
        const float* pc0 = (const float*)&c0; const float* pc1 = (const float*)&c1;
        const float* pc2 = (const float*)&c2;
        const float* pd0 = (const float*)&d0; const float* pd1 = (const float*)&d1;
        const float* pd2 = (const float*)&d2;
        const float* pho = (const float*)&ho;
        float* pr = (float*)&res;
#pragma unroll
        for (int l = 0; l < 4; ++l) {
            float r  = sigmoidf_(pg0[l] + pd0[l] + xv * pw0[l] + pc0[l]);
            float z  = sigmoidf_(pg1[l] + pd1[l] + xv * pw1[l] + pc1[l]);
            float nn = tanhf(xv * pw2[l] + pc2[l] + r * (pg2[l] + pd2[l]));
            pr[l] = (1.f - z) * nn + z * pho[l];
        }
        *(float4*)(d_h0 + b * HH + n) = res;
        uint2 hv, lv;
        hv.x = pack_bf2(res.x, res.y);          hv.y = pack_bf2(res.z, res.w);
        lv.x = pack_bf2(bflo(res.x), bflo(res.y)); lv.y = pack_bf2(bflo(res.z), bflo(res.w));
        *(uint2*)(d_h0hi + b * HH + n) = hv;
        *(uint2*)(d_h0lo + b * HH + n) = lv;
    }
}

__device__ void actB(const float* __restrict__ bi1, const float* __restrict__ bh)
{
    int gtid = blockIdx.x * blockDim.x + threadIdx.x;
    int st   = gridDim.x * blockDim.x;
    for (int idx = gtid; idx < (BT * HH) / 4; idx += st) {
        int b = idx >> 7;
        int n = (idx & 127) << 2;
        const float* P0 = d_PB0 + b * NG + n;
        const float* P1 = d_PB1 + b * NG + n;
        float4 i0 = *(const float4*)(P0);
        float4 i1 = *(const float4*)(P0 + HH);
        float4 i2 = *(const float4*)(P0 + 2 * HH);
        float4 h0g = *(const float4*)(P1);
        float4 h1g = *(const float4*)(P1 + HH);
        float4 h2g = *(const float4*)(P1 + 2 * HH);
        float4 c0 = *(const float4*)(bi1 + n);
        float4 c1 = *(const float4*)(bi1 + HH + n);
        float4 c2 = *(const float4*)(bi1 + 2 * HH + n);
        float4 d0 = *(const float4*)(bh + NG + n);
        float4 d1 = *(const float4*)(bh + NG + HH + n);
        float4 d2 = *(const float4*)(bh + NG + 2 * HH + n);
        float4 ho = *(const float4*)(d_h1 + b * HH + n);
        float4 res;
        const float* pi0 = (const float*)&i0; const float* pi1 = (const float*)&i1;
        const float* pi2 = (const float*)&i2;
        const float* ph0 = (const float*)&h0g; const float* ph1 = (const float*)&h1g;
        const float* ph2 = (const float*)&h2g;
        const float* pc0 = (const float*)&c0; const float* pc1 = (const float*)&c1;
        const float* pc2 = (const float*)&c2;
        const float* pd0 = (const float*)&d0; const float* pd1 = (const float*)&d1;
        const float* pd2 = (const float*)&d2;
        const float* pho = (const float*)&ho;
        float* pr = (float*)&res;
#pragma unroll
        for (int l = 0; l < 4; ++l) {
            float r  = sigmoidf_(pi0[l] + pc0[l] + ph0[l] + pd0[l]);
            float z  = sigmoidf_(pi1[l] + pc1[l] + ph1[l] + pd1[l]);
            float nn = tanhf(pi2[l] + pc2[l] + r * (ph2[l] + pd2[l]));
            pr[l] = (1.f - z) * nn + z * pho[l];
        }
        *(float4*)(d_h1 + b * HH + n) = res;
        uint2 hv, lv;
        hv.x = pack_bf2(res.x, res.y);          hv.y = pack_bf2(res.z, res.w);
        lv.x = pack_bf2(bflo(res.x), bflo(res.y)); lv.y = pack_bf2(bflo(res.z), bflo(res.w));
        *(uint2*)(d_h1hi + b * HH + n) = hv;
        *(uint2*)(d_h1lo + b * HH + n) = lv;
    }
}

// ---------------- final FC ----------------
__device__ void fcOut(const float* __restrict__ fcw, const float* __restrict__ fcb,
                      float* __restrict__ out)
{
    __shared__ float red[2][8];
    if (blockIdx.x >= 128) return;
    for (int s = 0; s < 2; ++s) {
        int b = blockIdx.x * 2 + s;
        float p0 = 0.f, p1 = 0.f;
        for (int k = threadIdx.x; k < HH; k += NTHR) {
            float h = d_h1[b * HH + k];
            p0 += h * fcw[k];
            p1 += h * fcw[HH + k];
        }
#pragma unroll
        for (int o = 16; o; o >>= 1) {
            p0 += __shfl_down_sync(0xffffffffu, p0, o);
            p1 += __shfl_down_sync(0xffffffffu, p1, o);
        }
        int w = threadIdx.x >> 5;
        if ((threadIdx.x & 31) == 0) { red[0][w] = p0; red[1][w] = p1; }
        __syncthreads();
        if (threadIdx.x == 0) {
            float a0 = 0.f, a1 = 0.f;
#pragma unroll
            for (int ww = 0; ww < 8; ++ww) { a0 += red[0][ww]; a1 += red[1][ww]; }
            out[b * 2 + 0] = a0 + fcb[0];
            out[b * 2 + 1] = a1 + fcb[1];
        }
        __syncthreads();
    }
}

// ---------------- persistent kernel ----------------
__global__ void __launch_bounds__(NTHR, 1)
gru_persistent(const float* __restrict__ x,   const float* __restrict__ Wi0,
               const float* __restrict__ bi0, const float* __restrict__ Wi1,
               const float* __restrict__ bi1, const float* __restrict__ Wh,
               const float* __restrict__ bh,  const float* __restrict__ fcw,
               const float* __restrict__ fcb, float* __restrict__ out)
{
    extern __shared__ char smem[];

    // fixed tile assignment for this CTA
    const int u = blockIdx.x;
    const bool active = (u < 144);
    const int gsel = u / 48;           // 0: gi1, 1: gh1, 2: layer0-next
    const int tb   = u % 48;
    const int m0   = (tb / 24) * 128;
    const int n0   = (tb % 24) * 64;

    const __nv_bfloat16* Agh = (gsel == 1) ? d_h1hi : d_h0hi;
    const __nv_bfloat16* Agl = (gsel == 1) ? d_h1lo : d_h0lo;
    float* Cg = (gsel == 0) ? d_PB0 : ((gsel == 1) ? d_PB1 : d_GA);

    if (active) {
        const float* Wsl = (gsel == 0) ? (Wi1 + n0 * HH)
                         : (gsel == 1) ? (Wh + NG * HH + n0 * HH)
                                       : (Wh + n0 * HH);
        preloadW(Wsl, smem);
    }
    __syncthreads();

    actA(x, Wi0, bi0, bh, 0);          // h0(0); GA/h zeroed by init
    gridBarrier();

    for (int t = 0; t < TT - 1; ++t) {
        if (active) tileStep(Agh, Agl, Cg, m0, n0, smem);
        gridBarrier();
        actB(bi1, bh);                 // h1(t)
        actA(x, Wi0, bi0, bh, t + 1);  // h0(t+1)
        gridBarrier();
    }

    if (u < 96) tileStep(Agh, Agl, Cg, m0, n0, smem);   // last step: gi1+gh1 only
    gridBarrier();
    actB(bi1, bh);
    gridBarrier();

    fcOut(fcw, fcb, out);
}

// ---------------- launch ----------------
extern "C" void kernel_launch(void* const* d_in, const int* in_sizes, int n_in,
                              void* d_out, int out_size)
{
    (void)in_sizes; (void)n_in; (void)out_size;
    const float* x   = (const float*)d_in[0];
    const float* Wi0 = (const float*)d_in[1];
    const float* bi0 = (const float*)d_in[2];
    const float* Wi1 = (const float*)d_in[3];
    const float* bi1 = (const float*)d_in[4];
    const float* Wh  = (const float*)d_in[5];
    const float* bh  = (const float*)d_in[6];
    const float* fcw = (const float*)d_in[7];
    const float* fcb = (const float*)d_in[8];
    float* out = (float*)d_out;

    cudaFuncSetAttribute(gru_persistent,
                         cudaFuncAttributeMaxDynamicSharedMemorySize, SMEM_BYTES);

    gru_init<<<64, 256>>>();
    gru_persistent<<<NCTA, NTHR, SMEM_BYTES>>>(x, Wi0, bi0, Wi1, bi1, Wh, bh,
                                               fcw, fcb, out);
}

// round 11
// speedup vs baseline: 2.2326x; 1.1001x over previous
#include <cuda_runtime.h>
#include <cuda_bf16.h>
#include <math.h>

// GRU: B=256, T=512, H=512, L=2, O=2.
// Persistent kernel; bf16 hi/lo split GEMM on mma.sync.m16n8k16 (fp32 accum).
// tcgen05 is NOT available (harness ptxas targets sm_103, no 'a').
//
// 144 fixed 128x64 output tiles, one per CTA. Each CTA pins its 64x512 weight
// slice in smem (bf16 hi+lo) for the whole run. A (=h hi/lo) is staged per
// 32-k chunk through a 3-stage cp.async pipeline (hides L2 latency).
// Per step: tile-gemm wave; grid barrier; fused activations (emit h fp32 +
// bf16 hi/lo); grid barrier. Final: out = h1 @ fc_w^T + fc_b.

#define BT 256
#define TT 512
#define HH 512
#define NG 1536
#define NCTA 148
#define NTHR 256

#define WST 520                        // W smem row stride (bf16 elems)
#define AST 40                         // A smem row stride (bf16 elems)
#define SMEM_W (64 * WST * 2)          // 66,560 B per W array (hi or lo)
#define ABUF   (128 * AST * 2)         // 10,240 B per (stage, hi/lo)
#define W_OFF  0
#define A_OFF  (2 * SMEM_W)            // 133,120
#define NSTAGE 3
#define SMEM_BYTES (A_OFF + NSTAGE * 2 * ABUF)   // 194,560 B

// ---------------- persistent device state ----------------
__device__ __align__(16) float d_h0[BT * HH];
__device__ __align__(16) float d_h1[BT * HH];
__device__ __align__(16) __nv_bfloat16 d_h0hi[BT * HH];
__device__ __align__(16) __nv_bfloat16 d_h0lo[BT * HH];
__device__ __align__(16) __nv_bfloat16 d_h1hi[BT * HH];
__device__ __align__(16) __nv_bfloat16 d_h1lo[BT * HH];
__device__ __align__(16) float d_GA[BT * NG];
__device__ __align__(16) float d_PB0[BT * NG];
__device__ __align__(16) float d_PB1[BT * NG];
__device__ unsigned d_barCount;
__device__ volatile unsigned d_barGen;

__global__ void gru_init()
{
    int i  = blockIdx.x * blockDim.x + threadIdx.x;
    int st = gridDim.x * blockDim.x;
    for (int e = i; e < BT * HH; e += st) { d_h0[e] = 0.f; d_h1[e] = 0.f; }
    unsigned* z0 = (unsigned*)d_h0hi; unsigned* z1 = (unsigned*)d_h0lo;
    unsigned* z2 = (unsigned*)d_h1hi; unsigned* z3 = (unsigned*)d_h1lo;
    for (int e = i; e < (BT * HH) / 2; e += st) { z0[e] = 0u; z1[e] = 0u; z2[e] = 0u; z3[e] = 0u; }
    for (int e = i; e < BT * NG; e += st) d_GA[e] = 0.f;
    if (i == 0) { d_barCount = 0u; d_barGen = 0u; }
}

// ---------------- software grid barrier ----------------
__device__ __forceinline__ void gridBarrier()
{
    __syncthreads();
    if (threadIdx.x == 0) {
        __threadfence();
        unsigned gen = d_barGen;
        if (atomicAdd(&d_barCount, 1u) == (unsigned)gridDim.x - 1u) {
            d_barCount = 0u;
            __threadfence();
            d_barGen = gen + 1u;
        } else {
            while (d_barGen == gen) __nanosleep(64);
        }
        __threadfence();
    }
    __syncthreads();
}

// ---------------- cp.async + misc PTX ----------------
__device__ __forceinline__ unsigned s2u(const void* p)
{
    unsigned a;
    asm("{ .reg .u64 t; cvta.to.shared.u64 t, %1; cvt.u32.u64 %0, t; }" : "=r"(a) : "l"(p));
    return a;
}
#define CPA16(d, s)  asm volatile("cp.async.cg.shared.global [%0], [%1], 16;" :: "r"(d), "l"(s) : "memory")
#define CP_COMMIT()  asm volatile("cp.async.commit_group;" ::: "memory")
#define CP_WAIT2()   asm volatile("cp.async.wait_group 2;" ::: "memory")
#define CP_WAIT0()   asm volatile("cp.async.wait_group 0;" ::: "memory")

// mma.sync m16n8k16 row.col bf16 -> f32
#define MMA16816(C, A, b0, b1)                                                  \
    asm volatile("mma.sync.aligned.m16n8k16.row.col.f32.bf16.bf16.f32 "         \
                 "{%0,%1,%2,%3},{%4,%5,%6,%7},{%8,%9},{%0,%1,%2,%3};"           \
                 : "+f"((C)[0]), "+f"((C)[1]), "+f"((C)[2]), "+f"((C)[3])       \
                 : "r"((A)[0]), "r"((A)[1]), "r"((A)[2]), "r"((A)[3]),          \
                   "r"(b0), "r"(b1))

// ---------------- bf16 split helpers ----------------
__device__ __forceinline__ unsigned pack_bf2(float a, float b)
{
    __nv_bfloat162 t = __floats2bfloat162_rn(a, b);   // .x = a (low half)
    return *reinterpret_cast<unsigned*>(&t);
}
__device__ __forceinline__ float bflo(float v)
{
    return v - __bfloat162float(__float2bfloat16_rn(v));
}

// ---------------- one-time weight slice -> smem (bf16 hi/lo) ----------------
__device__ void preloadW(const float* __restrict__ Wsl, char* smem)
{
    __nv_bfloat16* Whi = (__nv_bfloat16*)(smem + W_OFF);
    __nv_bfloat16* Wlo = (__nv_bfloat16*)(smem + W_OFF + SMEM_W);
    for (int idx = threadIdx.x; idx < 64 * (HH / 4); idx += NTHR) {
        int n  = idx >> 7;             // 0..63
        int k4 = (idx & 127) << 2;     // 0..508
        float4 w = *(const float4*)(Wsl + n * HH + k4);
        uint2 hv, lv;
        hv.x = pack_bf2(w.x, w.y);             hv.y = pack_bf2(w.z, w.w);
        lv.x = pack_bf2(bflo(w.x), bflo(w.y)); lv.y = pack_bf2(bflo(w.z), bflo(w.w));
        *(uint2*)(Whi + n * WST + k4) = hv;
        *(uint2*)(Wlo + n * WST + k4) = lv;
    }
}

// ---------------- cp.async stage of one 32-k A chunk (hi+lo) ----------------
// thread t: row = t>>1 (0..127), half = t&1 (16 elems = 32B each), 4x CPA16.
__device__ __forceinline__ void issueChunk(const __nv_bfloat16* __restrict__ Ahi,
                                           const __nv_bfloat16* __restrict__ Alo,
                                           unsigned smem_u, int stage, int m0, int c)
{
    int t = threadIdx.x;
    int row = t >> 1, half = t & 1;
    const char* gh = (const char*)(Ahi + (m0 + row) * HH + c * 32 + half * 16);
    const char* gl = (const char*)(Alo + (m0 + row) * HH + c * 32 + half * 16);
    unsigned bh = smem_u + A_OFF + (stage * 2 + 0) * ABUF + row * (AST * 2) + half * 32;
    unsigned bl = smem_u + A_OFF + (stage * 2 + 1) * ABUF + row * (AST * 2) + half * 32;
    CPA16(bh, gh);      CPA16(bh + 16, gh + 16);
    CPA16(bl, gl);      CPA16(bl + 16, gl + 16);
}

// ---------------- per-step 128x64xK512 tile gemm (split bf16, fp32 accum) ----------------
__device__ void tileStep(const __nv_bfloat16* __restrict__ Agh,
                         const __nv_bfloat16* __restrict__ Agl,
                         float* __restrict__ Cg, int m0, int n0,
                         char* smem, unsigned smem_u)
{
    const __nv_bfloat16* Whi = (const __nv_bfloat16*)(smem + W_OFF);
    const __nv_bfloat16* Wlo = (const __nv_bfloat16*)(smem + W_OFF + SMEM_W);

    const int tid  = threadIdx.x;
    const int wid  = tid >> 5;
    const int lane = tid & 31;
    const int g    = lane >> 2;        // 0..7
    const int t4   = lane & 3;         // 0..3
    const int wm   = wid & 1;          // m half (64)
    const int wn   = wid >> 1;         // n quarter (16)

    int aoff[4];
#pragma unroll
    for (int ma = 0; ma < 4; ++ma)
        aoff[ma] = (wm * 64 + ma * 16 + g) * AST + 2 * t4;
    int boff[2];
#pragma unroll
    for (int na = 0; na < 2; ++na)
        boff[na] = (wn * 16 + na * 8 + g) * WST + 2 * t4;

    float acc[4][2][4];
#pragma unroll
    for (int ma = 0; ma < 4; ++ma)
#pragma unroll
        for (int na = 0; na < 2; ++na)
#pragma unroll
            for (int q = 0; q < 4; ++q) acc[ma][na][q] = 0.f;

    // prologue: fill 3 stages (previous step's reads are fenced by grid barrier)
#pragma unroll
    for (int s = 0; s < NSTAGE; ++s) {
        issueChunk(Agh, Agl, smem_u, s, m0, s);
        CP_COMMIT();
    }

#pragma unroll 1
    for (int c = 0; c < 16; ++c) {
        int stg = c % NSTAGE;
        CP_WAIT2();                // chunk c's group complete
        __syncthreads();

        const __nv_bfloat16* Ah = (const __nv_bfloat16*)(smem + A_OFF + (stg * 2 + 0) * ABUF);
        const __nv_bfloat16* Al = (const __nv_bfloat16*)(smem + A_OFF + (stg * 2 + 1) * ABUF);
#pragma unroll
        for (int ks = 0; ks < 32; ks += 16) {
            unsigned ah[4][4], al[4][4];
#pragma unroll
            for (int ma = 0; ma < 4; ++ma) {
                int o = aoff[ma] + ks;
                ah[ma][0] = *(const unsigned*)(Ah + o);
                ah[ma][1] = *(const unsigned*)(Ah + o + 8 * AST);
                ah[ma][2] = *(const unsigned*)(Ah + o + 8);
                ah[ma][3] = *(const unsigned*)(Ah + o + 8 * AST + 8);
                al[ma][0] = *(const unsigned*)(Al + o);
                al[ma][1] = *(const unsigned*)(Al + o + 8 * AST);
                al[ma][2] = *(const unsigned*)(Al + o + 8);
                al[ma][3] = *(const unsigned*)(Al + o + 8 * AST + 8);
            }
#pragma unroll
            for (int na = 0; na < 2; ++na) {
                int ob = boff[na] + c * 32 + ks;
                unsigned bh0 = *(const unsigned*)(Whi + ob);
                unsigned bh1 = *(const unsigned*)(Whi + ob + 8);
                unsigned bl0 = *(const unsigned*)(Wlo + ob);
                unsigned bl1 = *(const unsigned*)(Wlo + ob + 8);
#pragma unroll
                for (int ma = 0; ma < 4; ++ma) {
                    MMA16816(acc[ma][na], ah[ma], bh0, bh1);   // hi*hi
                    MMA16816(acc[ma][na], ah[ma], bl0, bl1);   // hi*lo
                    MMA16816(acc[ma][na], al[ma], bh0, bh1);   // lo*hi
                }
            }
        }

        __syncthreads();           // all warps done reading stage stg
        if (c + NSTAGE < 16)
            issueChunk(Agh, Agl, smem_u, stg, m0, c + NSTAGE);
        CP_COMMIT();               // commit (possibly empty) to keep group count
    }
    CP_WAIT0();                    // drain (no pending real groups remain)

    // epilogue: per-lane fragment layout of C (m16n8)
#pragma unroll
    for (int ma = 0; ma < 4; ++ma) {
        int row = m0 + wm * 64 + ma * 16 + g;
#pragma unroll
        for (int na = 0; na < 2; ++na) {
            int col = n0 + wn * 16 + na * 8 + 2 * t4;
            float2 v0; v0.x = acc[ma][na][0]; v0.y = acc[ma][na][1];
            float2 v1; v1.x = acc[ma][na][2]; v1.y = acc[ma][na][3];
            *(float2*)(Cg + row * NG + col)       = v0;
            *(float2*)(Cg + (row + 8) * NG + col) = v1;
        }
    }
}

// ---------------- activations (exact; also emit bf16 hi/lo of h) ----------------
__device__ __forceinline__ float sigmoidf_(float v) { return 1.f / (1.f + expf(-v)); }

__device__ void actA(const float* __restrict__ x, const float* __restrict__ Wi0,
                     const float* __restrict__ bi0, const float* __restrict__ bh, int t)
{
    int gtid = blockIdx.x * blockDim.x + threadIdx.x;
    int st   = gridDim.x * blockDim.x;
    for (int idx = gtid; idx < (BT * HH) / 4; idx += st) {
        int b = idx >> 7;
        int n = (idx & 127) << 2;
        float xv = x[b * TT + t];
        const float* G = d_GA + b * NG + n;
        float4 g0 = *(const float4*)(G);
        float4 g1 = *(const float4*)(G + HH);
        float4 g2 = *(const float4*)(G + 2 * HH);
        float4 w0 = *(const float4*)(Wi0 + n);
        float4 w1 = *(const float4*)(Wi0 + HH + n);
        float4 w2 = *(const float4*)(Wi0 + 2 * HH + n);
        float4 c0 = *(const float4*)(bi0 + n);
        float4 c1 = *(const float4*)(bi0 + HH + n);
        float4 c2 = *(const float4*)(bi0 + 2 * HH + n);
        float4 d0 = *(const float4*)(bh + n);
        float4 d1 = *(const float4*)(bh + HH + n);
        float4 d2 = *(const float4*)(bh + 2 * HH + n);
        float4 ho = *(const float4*)(d_h0 + b * HH + n);
        float4 res;
        const float* pg0 = (const float*)&g0; const float* pg1 = (const float*)&g1;
        const float* pg2 = (const float*)&g2;
        const float* pw0 = (const float*)&w0; const float* pw1 = (const float*)&w1;
        const float* pw2 = (const float*)&w2;
        const float* pc0 = (const float*)&c0; const float* pc1 = (const float*)&c1;
        const float* pc2 = (const float*)&c2;
        const float* pd0 = (const float*)&d0; const float* pd1 = (const float*)&d1;
        const float* pd2 = (const float*)&d2;
        const float* pho = (const float*)&ho;
        float* pr = (float*)&res;
#pragma unroll
        for (int l = 0; l < 4; ++l) {
            float r  = sigmoidf_(pg0[l] + pd0[l] + xv * pw0[l] + pc0[l]);
            float z  = sigmoidf_(pg1[l] + pd1[l] + xv * pw1[l] + pc1[l]);
            float nn = tanhf(xv * pw2[l] + pc2[l] + r * (pg2[l] + pd2[l]));
            pr[l] = (1.f - z) * nn + z * pho[l];
        }
        *(float4*)(d_h0 + b * HH + n) = res;
        uint2 hv, lv;
        hv.x = pack_bf2(res.x, res.y);             hv.y = pack_bf2(res.z, res.w);
        lv.x = pack_bf2(bflo(res.x), bflo(res.y)); lv.y = pack_bf2(bflo(res.z), bflo(res.w));
        *(uint2*)(d_h0hi + b * HH + n) = hv;
        *(uint2*)(d_h0lo + b * HH + n) = lv;
    }
}

__device__ void actB(const float* __restrict__ bi1, const float* __restrict__ bh)
{
    int gtid = blockIdx.x * blockDim.x + threadIdx.x;
    int st   = gridDim.x * blockDim.x;
    for (int idx = gtid; idx < (BT * HH) / 4; idx += st) {
        int b = idx >> 7;
        int n = (idx & 127) << 2;
        const float* P0 = d_PB0 + b * NG + n;
        const float* P1 = d_PB1 + b * NG + n;
        float4 i0 = *(const float4*)(P0);
        float4 i1 = *(const float4*)(P0 + HH);
        float4 i2 = *(const float4*)(P0 + 2 * HH);
        float4 h0g = *(const float4*)(P1);
        float4 h1g = *(const float4*)(P1 + HH);
        float4 h2g = *(const float4*)(P1 + 2 * HH);
        float4 c0 = *(const float4*)(bi1 + n);
        float4 c1 = *(const float4*)(bi1 + HH + n);
        float4 c2 = *(const float4*)(bi1 + 2 * HH + n);
        float4 d0 = *(const float4*)(bh + NG + n);
        float4 d1 = *(const float4*)(bh + NG + HH + n);
        float4 d2 = *(const float4*)(bh + NG + 2 * HH + n);
        float4 ho = *(const float4*)(d_h1 + b * HH + n);
        float4 res;
        const float* pi0 = (const float*)&i0; const float* pi1 = (const float*)&i1;
        const float* pi2 = (const float*)&i2;
        const float* ph0 = (const float*)&h0g; const float* ph1 = (const float*)&h1g;
        const float* ph2 = (const float*)&h2g;
        const float* pc0 = (const float*)&c0; const float* pc1 = (const float*)&c1;
        const float* pc2 = (const float*)&c2;
        const float* pd0 = (const float*)&d0; const float* pd1 = (const float*)&d1;
        const float* pd2 = (const float*)&d2;
        const float* pho = (const float*)&ho;
        float* pr = (float*)&res;
#pragma unroll
        for (int l = 0; l < 4; ++l) {
            float r  = sigmoidf_(pi0[l] + pc0[l] + ph0[l] + pd0[l]);
            float z  = sigmoidf_(pi1[l] + pc1[l] + ph1[l] + pd1[l]);
            float nn = tanhf(pi2[l] + pc2[l] + r * (ph2[l] + pd2[l]));
            pr[l] = (1.f - z) * nn + z * pho[l];
        }
        *(float4*)(d_h1 + b * HH + n) = res;
        uint2 hv, lv;
        hv.x = pack_bf2(res.x, res.y);             hv.y = pack_bf2(res.z, res.w);
        lv.x = pack_bf2(bflo(res.x), bflo(res.y)); lv.y = pack_bf2(bflo(res.z), bflo(res.w));
        *(uint2*)(d_h1hi + b * HH + n) = hv;
        *(uint2*)(d_h1lo + b * HH + n) = lv;
    }
}

// ---------------- final FC ----------------
__device__ void fcOut(const float* __restrict__ fcw, const float* __restrict__ fcb,
                      float* __restrict__ out)
{
    __shared__ float red[2][8];
    if (blockIdx.x >= 128) return;
    for (int s = 0; s < 2; ++s) {
        int b = blockIdx.x * 2 + s;
        float p0 = 0.f, p1 = 0.f;
        for (int k = threadIdx.x; k < HH; k += NTHR) {
            float h = d_h1[b * HH + k];
            p0 += h * fcw[k];
            p1 += h * fcw[HH + k];
        }
#pragma unroll
        for (int o = 16; o; o >>= 1) {
            p0 += __shfl_down_sync(0xffffffffu, p0, o);
            p1 += __shfl_down_sync(0xffffffffu, p1, o);
        }
        int w = threadIdx.x >> 5;
        if ((threadIdx.x & 31) == 0) { red[0][w] = p0; red[1][w] = p1; }
        __syncthreads();
        if (threadIdx.x == 0) {
            float a0 = 0.f, a1 = 0.f;
#pragma unroll
            for (int ww = 0; ww < 8; ++ww) { a0 += red[0][ww]; a1 += red[1][ww]; }
            out[b * 2 + 0] = a0 + fcb[0];
            out[b * 2 + 1] = a1 + fcb[1];
        }
        __syncthreads();
    }
}

// ---------------- persistent kernel ----------------
__global__ void __launch_bounds__(NTHR, 1)
gru_persistent(const float* __restrict__ x,   const float* __restrict__ Wi0,
               const float* __restrict__ bi0, const float* __restrict__ Wi1,
               const float* __restrict__ bi1, const float* __restrict__ Wh,
               const float* __restrict__ bh,  const float* __restrict__ fcw,
               const float* __restrict__ fcb, float* __restrict__ out)
{
    extern __shared__ char smem[];
    const unsigned smem_u = s2u(smem);

    // fixed tile assignment
    const int u = blockIdx.x;
    const bool active = (u < 144);
    const int gsel = u / 48;           // 0: gi1, 1: gh1, 2: layer0-next
    const int tb   = u % 48;
    const int m0   = (tb / 24) * 128;
    const int n0   = (tb % 24) * 64;

    const __nv_bfloat16* Agh = (gsel == 1) ? d_h1hi : d_h0hi;
    const __nv_bfloat16* Agl = (gsel == 1) ? d_h1lo : d_h0lo;
    float* Cg = (gsel == 0) ? d_PB0 : ((gsel == 1) ? d_PB1 : d_GA);

    if (active) {
        const float* Wsl = (gsel == 0) ? (Wi1 + n0 * HH)
                         : (gsel == 1) ? (Wh + NG * HH + n0 * HH)
                                       : (Wh + n0 * HH);
        preloadW(Wsl, smem);
    }
    __syncthreads();

    actA(x, Wi0, bi0, bh, 0);          // h0(0); GA/h zeroed by init
    gridBarrier();

    for (int t = 0; t < TT - 1; ++t) {
        if (active) tileStep(Agh, Agl, Cg, m0, n0, smem, smem_u);
        gridBarrier();
        actB(bi1, bh);                 // h1(t)
        actA(x, Wi0, bi0, bh, t + 1);  // h0(t+1)
        gridBarrier();
    }

    if (u < 96) tileStep(Agh, Agl, Cg, m0, n0, smem, smem_u);   // last step
    gridBarrier();
    actB(bi1, bh);
    gridBarrier();

    fcOut(fcw, fcb, out);
}

// ---------------- launch ----------------
extern "C" void kernel_launch(void* const* d_in, const int* in_sizes, int n_in,
                              void* d_out, int out_size)
{
    (void)in_sizes; (void)n_in; (void)out_size;
    const float* x   = (const float*)d_in[0];
    const float* Wi0 = (const float*)d_in[1];
    const float* bi0 = (const float*)d_in[2];
    const float* Wi1 = (const float*)d_in[3];
    const float* bi1 = (const float*)d_in[4];
    const float* Wh  = (const float*)d_in[5];
    const float* bh  = (const float*)d_in[6];
    const float* fcw = (const float*)d_in[7];
    const float* fcb = (const float*)d_in[8];
    float* out = (float*)d_out;

    cudaFuncSetAttribute(gru_persistent,
                         cudaFuncAttributeMaxDynamicSharedMemorySize, SMEM_BYTES);

    gru_init<<<64, 256>>>();
    gru_persistent<<<NCTA, NTHR, SMEM_BYTES>>>(x, Wi0, bi0, Wi1, bi1, Wh, bh,
                                               fcw, fcb, out);
}